// round 8
// baseline (speedup 1.0000x reference)
#include <cuda_runtime.h>
#include <cuda_fp16.h>
#include <cstdint>

#define EPS     1e-10f
#define B_CONST 1.15f
#define BR      1.05f
#define HW      (512 * 512)

#define CLUSTER      8
#define TPB          1024
#define NCTAS        144                 // 18 clusters of 8; <= 148 SMs, 1 CTA/SM
#define SHARD        (HW / CLUSTER)      // 32768 entries per CTA
#define SHARD_BYTES  (SHARD * 4)         // 128 KB

// Global staging table: (v, 1/(v+eps)) as half2, 1 MB.
__device__ __half2 g_tab[HW];

// ---------------------------------------------------------------------------
// Build the fp16 packed table (vectorized: 4 pixels/thread).
__global__ void __launch_bounds__(256) build_v_kernel(const float4* __restrict__ vin4,
                                                      float* __restrict__ out) {
    int t = blockIdx.x * blockDim.x + threadIdx.x;
    if (t < HW / 4) {
        float4 a = vin4[t];
        float4 b = vin4[t + HW / 4];
        float4 c = vin4[t + 2 * (HW / 4)];

        float v0 = ((a.x + b.x + c.x) * (1.0f/3.0f) * 255.0f + 1.0f) * (1.0f/256.0f);
        float v1 = ((a.y + b.y + c.y) * (1.0f/3.0f) * 255.0f + 1.0f) * (1.0f/256.0f);
        float v2 = ((a.z + b.z + c.z) * (1.0f/3.0f) * 255.0f + 1.0f) * (1.0f/256.0f);
        float v3 = ((a.w + b.w + c.w) * (1.0f/3.0f) * 255.0f + 1.0f) * (1.0f/256.0f);

        uint2* dst = reinterpret_cast<uint2*>(g_tab);
        __half2 h0 = __floats2half2_rn(v0, __frcp_rn(v0 + EPS));
        __half2 h1 = __floats2half2_rn(v1, __frcp_rn(v1 + EPS));
        __half2 h2 = __floats2half2_rn(v2, __frcp_rn(v2 + EPS));
        __half2 h3 = __floats2half2_rn(v3, __frcp_rn(v3 + EPS));
        dst[2 * t + 0] = make_uint2(*(uint32_t*)&h0, *(uint32_t*)&h1);
        dst[2 * t + 1] = make_uint2(*(uint32_t*)&h2, *(uint32_t*)&h3);
    }
    if (t == 0) out[0] = 0.0f;
}

// ---------------------------------------------------------------------------
__device__ __forceinline__ uint32_t smem_u32(const void* p) {
    return (uint32_t)__cvta_generic_to_shared(p);
}

// DSMEM lookup: idx -> (cluster rank, offset); mapa + ld.shared::cluster.
__device__ __forceinline__ float2 tab_lookup(uint32_t tab_base, int idx) {
    uint32_t rank = ((uint32_t)idx) >> 15;               // idx / SHARD
    uint32_t addr = tab_base + ((((uint32_t)idx) & 32767u) << 2);
    uint32_t raddr, bits;
    asm("mapa.shared::cluster.u32 %0, %1, %2;" : "=r"(raddr) : "r"(addr), "r"(rank));
    asm("ld.shared::cluster.b32 %0, [%1];" : "=r"(bits) : "r"(raddr));
    __half2 h = *reinterpret_cast<__half2*>(&bits);
    return __half22float2(h);
}

// ---------------------------------------------------------------------------
// Loss kernel: table distributed across an 8-CTA cluster's SMEM.
// Gathers ride the smem crossbar / DSMEM fabric, leaving L1tex to streaming.
__global__ void __cluster_dims__(CLUSTER, 1, 1) __launch_bounds__(TPB, 1)
whdr_loss_kernel(const int4*  __restrict__ coords,
                 const int*   __restrict__ darker,
                 const float* __restrict__ weights,
                 float* __restrict__ out,
                 int n)
{
    extern __shared__ uint4 smem_dyn[];                  // 128 KB table shard
    uint32_t tab_base = smem_u32(smem_dyn);

    const float inv_b = 1.0f / B_CONST;
    const float bl    = 1.0f / BR;
    const float inv_n = 1.0f / (float)n;

    int tid = threadIdx.x;

    // Load this CTA's shard: entries [rank*SHARD, (rank+1)*SHARD).
    uint32_t rank;
    asm("mov.u32 %0, %%cluster_ctarank;" : "=r"(rank));
    {
        const uint4* src = reinterpret_cast<const uint4*>(g_tab) + (size_t)rank * (SHARD_BYTES / 16);
        #pragma unroll
        for (int j = 0; j < SHARD_BYTES / 16 / TPB; j++)   // 8 iters
            smem_dyn[tid + j * TPB] = src[tid + j * TPB];
    }
    // All shards visible cluster-wide before any lookup.
    asm volatile("barrier.cluster.arrive.aligned;" ::: "memory");
    asm volatile("barrier.cluster.wait.aligned;"   ::: "memory");

    float acc = 0.0f;

    int stride = gridDim.x * blockDim.x;                 // 147456
    #pragma unroll 4
    for (int i = blockIdx.x * blockDim.x + tid; i < n; i += stride) {
        int4 c  = coords[i];
        int  d  = darker[i];
        float w = weights[i];

        int i1 = (c.y << 9) | c.x;
        int i2 = (c.w << 9) | c.z;

        float2 p1 = tab_lookup(tab_base, i1);            // (r1, 1/(r1+eps))
        float2 p2 = tab_lookup(tab_base, i2);            // (r2, 1/(r2+eps))

        float ratio     = p1.x * p2.y;
        float ratio_inv = p2.x * p1.y;

        float l1 = (ratio > inv_b)   ? (ratio - inv_b + (B_CONST - ratio_inv)) : 0.0f;
        float l2 = (ratio < B_CONST) ? (B_CONST - ratio + (ratio_inv - inv_b)) : 0.0f;
        float l0 = (ratio > BR) ? (ratio - BR + (bl - ratio_inv))
                 : ((ratio < bl) ? (bl - ratio + (ratio_inv - BR)) : 0.0f);

        float per = (d == 1) ? l1 : ((d == 2) ? l2 : l0);
        acc += w * per;
    }

    // Warp reduction
    #pragma unroll
    for (int off = 16; off > 0; off >>= 1)
        acc += __shfl_xor_sync(0xffffffffu, acc, off);

    // Block reduction (32 warps)
    __shared__ float warp_sums[32];
    int lane = tid & 31;
    int wid  = tid >> 5;
    if (lane == 0) warp_sums[wid] = acc;
    __syncthreads();
    if (wid == 0) {
        float s = warp_sums[lane];
        #pragma unroll
        for (int off = 16; off > 0; off >>= 1)
            s += __shfl_xor_sync(0xffffffffu, s, off);
        if (lane == 0)
            atomicAdd(out, s * inv_n);
    }

    // No CTA may exit while peers might still read its shard.
    asm volatile("barrier.cluster.arrive.aligned;" ::: "memory");
    asm volatile("barrier.cluster.wait.aligned;"   ::: "memory");
}

extern "C" void kernel_launch(void* const* d_in, const int* in_sizes, int n_in,
                              void* d_out, int out_size)
{
    const float4* vin4    = (const float4*)d_in[0];
    const int4*   coords  = (const int4*)d_in[1];
    const int*    darker  = (const int*)d_in[2];
    const float*  weights = (const float*)d_in[3];
    float*        out     = (float*)d_out;

    int n = in_sizes[2];  // darker element count == N

    static bool attr_set = false;
    if (!attr_set) {
        cudaFuncSetAttribute(whdr_loss_kernel,
                             cudaFuncAttributeMaxDynamicSharedMemorySize,
                             SHARD_BYTES);
        attr_set = true;
    }

    build_v_kernel<<<(HW / 4 + 255) / 256, 256>>>(vin4, out);

    whdr_loss_kernel<<<NCTAS, TPB, SHARD_BYTES>>>(coords, darker, weights, out, n);
}

// round 9
// speedup vs baseline: 4.7084x; 4.7084x over previous
#include <cuda_runtime.h>

// Constants from the reference
#define EPS     1e-10f
#define B_CONST (1.0f + 0.1f + 0.05f)   // 1.15
#define BR      (1.0f + 0.1f - 0.05f)   // 1.05
#define HW      (512 * 512)

// Packed table: .x = v, .y = 1/(v+EPS). One 8B gather returns both values.
__device__ float2 g_vv[HW];

// Vectorized table build: 4 pixels per thread, float4 loads/stores.
__global__ void __launch_bounds__(256) build_v_kernel(const float4* __restrict__ vin4,
                                                      float* __restrict__ out) {
    int t = blockIdx.x * blockDim.x + threadIdx.x;
    if (t < HW / 4) {
        float4 a = vin4[t];
        float4 b = vin4[t + HW / 4];
        float4 c = vin4[t + 2 * (HW / 4)];
        float4* dst = reinterpret_cast<float4*>(g_vv);

        float v0 = ((a.x + b.x + c.x) * (1.0f/3.0f) * 255.0f + 1.0f) * (1.0f/256.0f);
        float v1 = ((a.y + b.y + c.y) * (1.0f/3.0f) * 255.0f + 1.0f) * (1.0f/256.0f);
        float v2 = ((a.z + b.z + c.z) * (1.0f/3.0f) * 255.0f + 1.0f) * (1.0f/256.0f);
        float v3 = ((a.w + b.w + c.w) * (1.0f/3.0f) * 255.0f + 1.0f) * (1.0f/256.0f);

        dst[2 * t + 0] = make_float4(v0, __frcp_rn(v0 + EPS), v1, __frcp_rn(v1 + EPS));
        dst[2 * t + 1] = make_float4(v2, __frcp_rn(v2 + EPS), v3, __frcp_rn(v3 + EPS));
    }
    if (t == 0) out[0] = 0.0f;
}

// R2 loss kernel (proven floor-bound config) + PDL: the grid launches while
// build_v_kernel is still running; we wait only before the first g_vv access.
__global__ void __launch_bounds__(256) whdr_loss_kernel(
    const int4*  __restrict__ coords,    // (N,4) int32 as int4: x1,y1,x2,y2
    const int*   __restrict__ darker,    // (N,)
    const float* __restrict__ weights,   // (N,)
    float* __restrict__ out,
    int n)
{
    const float inv_b = 1.0f / B_CONST;
    const float bl    = 1.0f / BR;
    const float inv_n = 1.0f / (float)n;

    // Prologue (independent of g_vv): first-iteration streaming loads.
    int tid0   = blockIdx.x * blockDim.x + threadIdx.x;
    int stride = gridDim.x * blockDim.x;

    int4  c_pre = (tid0 < n) ? coords[tid0] : make_int4(0, 0, 0, 0);
    int   d_pre = (tid0 < n) ? darker[tid0] : 0;
    float w_pre = (tid0 < n) ? weights[tid0] : 0.0f;

    // Wait for build_v_kernel (PDL dependency) before touching g_vv / out.
    cudaGridDependencySynchronize();

    float acc = 0.0f;

    if (tid0 < n) {
        int i1 = (c_pre.y << 9) | c_pre.x;
        int i2 = (c_pre.w << 9) | c_pre.z;
        float2 p1 = __ldg(&g_vv[i1]);
        float2 p2 = __ldg(&g_vv[i2]);
        float ratio     = p1.x * p2.y;
        float ratio_inv = p2.x * p1.y;
        float l1 = (ratio > inv_b)   ? (ratio - inv_b + (B_CONST - ratio_inv)) : 0.0f;
        float l2 = (ratio < B_CONST) ? (B_CONST - ratio + (ratio_inv - inv_b)) : 0.0f;
        float l0 = (ratio > BR) ? (ratio - BR + (bl - ratio_inv))
                 : ((ratio < bl) ? (bl - ratio + (ratio_inv - BR)) : 0.0f);
        acc = w_pre * ((d_pre == 1) ? l1 : ((d_pre == 2) ? l2 : l0));
    }

    #pragma unroll 4
    for (int i = tid0 + stride; i < n; i += stride) {
        int4 c  = coords[i];
        int  d  = darker[i];
        float w = weights[i];

        int i1 = (c.y << 9) | c.x;   // y1*512 + x1
        int i2 = (c.w << 9) | c.z;   // y2*512 + x2

        float2 p1 = __ldg(&g_vv[i1]);   // (r1, 1/(r1+eps))
        float2 p2 = __ldg(&g_vv[i2]);   // (r2, 1/(r2+eps))

        float ratio     = p1.x * p2.y;  // r1 / (r2 + EPS)
        float ratio_inv = p2.x * p1.y;  // r2 / (r1 + EPS)

        float l1 = (ratio > inv_b)   ? (ratio - inv_b + (B_CONST - ratio_inv)) : 0.0f;
        float l2 = (ratio < B_CONST) ? (B_CONST - ratio + (ratio_inv - inv_b)) : 0.0f;
        float l0 = (ratio > BR) ? (ratio - BR + (bl - ratio_inv))
                 : ((ratio < bl) ? (bl - ratio + (ratio_inv - BR)) : 0.0f);

        float per = (d == 1) ? l1 : ((d == 2) ? l2 : l0);
        acc += w * per;
    }

    // Warp reduction
    #pragma unroll
    for (int off = 16; off > 0; off >>= 1)
        acc += __shfl_xor_sync(0xffffffffu, acc, off);

    // Block reduction
    __shared__ float warp_sums[8];
    int lane = threadIdx.x & 31;
    int wid  = threadIdx.x >> 5;
    if (lane == 0) warp_sums[wid] = acc;
    __syncthreads();
    if (wid == 0) {
        float s = (lane < (blockDim.x >> 5)) ? warp_sums[lane] : 0.0f;
        #pragma unroll
        for (int off = 4; off > 0; off >>= 1)
            s += __shfl_xor_sync(0xffffffffu, s, off);
        if (lane == 0)
            atomicAdd(out, s * inv_n);
    }
}

extern "C" void kernel_launch(void* const* d_in, const int* in_sizes, int n_in,
                              void* d_out, int out_size)
{
    const float4* vin4    = (const float4*)d_in[0];
    const int4*   coords  = (const int4*)d_in[1];
    const int*    darker  = (const int*)d_in[2];
    const float*  weights = (const float*)d_in[3];
    float*        out     = (float*)d_out;

    int n = in_sizes[2];  // darker element count == N

    build_v_kernel<<<(HW / 4 + 255) / 256, 256>>>(vin4, out);

    // Loss kernel with programmatic dependent launch: overlaps its launch +
    // prologue with build_v_kernel's tail.
    cudaLaunchConfig_t cfg = {};
    cfg.gridDim  = dim3(2048, 1, 1);   // 16 elts/thread, exact fit for N=8388608
    cfg.blockDim = dim3(256, 1, 1);
    cudaLaunchAttribute attrs[1];
    attrs[0].id = cudaLaunchAttributeProgrammaticStreamSerialization;
    attrs[0].val.programmaticStreamSerializationAllowed = 1;
    cfg.attrs    = attrs;
    cfg.numAttrs = 1;
    cudaLaunchKernelEx(&cfg, whdr_loss_kernel, coords, darker, weights, out, n);
}